// round 5
// baseline (speedup 1.0000x reference)
#include <cuda_runtime.h>

// B=4096, NSPIN=2, NPS=16, D=256, NION=8, DIM=3. One block per (b,s) pair.
struct __align__(16) Smem {
    float xsT[256 * 17];      // [d][n]
    float W[256 * 17];        // [d][o]
    float part[16 * 16 * 16]; // [kg][n][o]
    float rs[16 * 24];        // [n][i*3+d]
    float ed[8 * 16 * 9];     // [i][o][e*3+d]
    float ei[8 * 16];         // [i][o]
    float A[16 * 18];         // augmented [M^T | rhs], pitch 18
    float M0[16];
    float det;
    int   piv;
};

__global__ void __launch_bounds__(256, 1)
cof_kernel(const float* __restrict__ eq,  const float* __restrict__ rei,
           const float* __restrict__ Wg,  const float* __restrict__ bg,
           const float* __restrict__ edg, const float* __restrict__ eig,
           float* __restrict__ out)
{
    extern __shared__ __align__(16) char smem_raw[];
    Smem& S = *reinterpret_cast<Smem*>(smem_raw);
    const int p = blockIdx.x, s = p & 1, t = threadIdx.x;

    // ---- Phase 0: loads ----
    {
        const float* xsrc = eq + (size_t)p * 4096;
        #pragma unroll
        for (int c = 0; c < 4; ++c) {
            int idx = c * 1024 + t * 4;
            float4 v = *reinterpret_cast<const float4*>(xsrc + idx);
            int n = idx >> 8, d = idx & 255;
            S.xsT[(d+0)*17+n]=v.x; S.xsT[(d+1)*17+n]=v.y;
            S.xsT[(d+2)*17+n]=v.z; S.xsT[(d+3)*17+n]=v.w;
        }
        const float* wsrc = Wg + s * 4096;
        #pragma unroll
        for (int c = 0; c < 4; ++c) {
            int idx = c * 1024 + t * 4;
            float4 v = *reinterpret_cast<const float4*>(wsrc + idx);
            int d = idx >> 4, o = idx & 15;
            S.W[d*17+o+0]=v.x; S.W[d*17+o+1]=v.y;
            S.W[d*17+o+2]=v.z; S.W[d*17+o+3]=v.w;
        }
        if (t < 96)
            *reinterpret_cast<float4*>(&S.rs[t*4]) =
                *reinterpret_cast<const float4*>(rei + (size_t)p*384 + t*4);
        for (int i = t * 4; i < 1152; i += 1024)
            *reinterpret_cast<float4*>(&S.ed[i]) =
                *reinterpret_cast<const float4*>(edg + s*1152 + i);
        if (t < 32)
            *reinterpret_cast<float4*>(&S.ei[t*4]) =
                *reinterpret_cast<const float4*>(eig + s*128 + t*4);
    }
    __syncthreads();

    // ---- Phase 1: GEMM, K split 16 ways, 4x4 tiles ----
    {
        const int kg = t >> 4, tl = t & 15;
        const int tn = (tl >> 2) << 2, to = (tl & 3) << 2;
        float a[4][4] = {};
        const int d0 = kg << 4;
        #pragma unroll
        for (int j = 0; j < 16; ++j) {
            const float* xr = &S.xsT[(d0+j)*17 + tn];
            const float* wr = &S.W  [(d0+j)*17 + to];
            float x0=xr[0],x1=xr[1],x2=xr[2],x3=xr[3];
            float w0=wr[0],w1=wr[1],w2=wr[2],w3=wr[3];
            a[0][0]=fmaf(x0,w0,a[0][0]); a[0][1]=fmaf(x0,w1,a[0][1]);
            a[0][2]=fmaf(x0,w2,a[0][2]); a[0][3]=fmaf(x0,w3,a[0][3]);
            a[1][0]=fmaf(x1,w0,a[1][0]); a[1][1]=fmaf(x1,w1,a[1][1]);
            a[1][2]=fmaf(x1,w2,a[1][2]); a[1][3]=fmaf(x1,w3,a[1][3]);
            a[2][0]=fmaf(x2,w0,a[2][0]); a[2][1]=fmaf(x2,w1,a[2][1]);
            a[2][2]=fmaf(x2,w2,a[2][2]); a[2][3]=fmaf(x2,w3,a[2][3]);
            a[3][0]=fmaf(x3,w0,a[3][0]); a[3][1]=fmaf(x3,w1,a[3][1]);
            a[3][2]=fmaf(x3,w2,a[3][2]); a[3][3]=fmaf(x3,w3,a[3][3]);
        }
        #pragma unroll
        for (int r = 0; r < 4; ++r)
            *reinterpret_cast<float4*>(&S.part[(kg*16 + tn + r)*16 + to]) =
                make_float4(a[r][0], a[r][1], a[r][2], a[r][3]);
    }
    __syncthreads();

    // ---- Phase 2: reduce + envelope + M ----
    const int n = t >> 4, o = t & 15;
    {
        float y = __ldg(bg + s*16 + o);
        #pragma unroll
        for (int k = 0; k < 16; ++k) y += S.part[(k*16 + n)*16 + o];

        float env = 0.f;
        #pragma unroll
        for (int i = 0; i < 8; ++i) {
            float r0=S.rs[n*24+i*3+0], r1=S.rs[n*24+i*3+1], r2=S.rs[n*24+i*3+2];
            const float* E = &S.ed[(i*16+o)*9];
            float a0 = fmaf(E[0],r0, fmaf(E[1],r1, E[2]*r2));
            float a1 = fmaf(E[3],r0, fmaf(E[4],r1, E[5]*r2));
            float a2 = fmaf(E[6],r0, fmaf(E[7],r1, E[8]*r2));
            float q  = fmaf(a0,a0, fmaf(a1,a1, a2*a2));
            env = fmaf(expf(-sqrtf(q)), S.ei[i*16+o], env);
        }
        float Mv = y * env;
        S.A[o*18 + n] = Mv;                 // A = M^T
        if (o == 0) S.M0[n] = Mv;
        if (t < 16) S.A[t*18 + 16] = (t == 0) ? 1.f : 0.f;
        if (t == 0) S.det = 1.f;
    }
    __syncthreads();

    // ---- Phase 3: pivoted GE on [M^T | e0], track det ----
    for (int k = 0; k < 16; ++k) {
        if (t == 0) {
            int piv = k; float best = fabsf(S.A[k*18+k]);
            for (int r = k+1; r < 16; ++r) {
                float v = fabsf(S.A[r*18+k]);
                if (v > best) { best = v; piv = r; }
            }
            S.piv = piv;
        }
        __syncthreads();
        const int piv = S.piv;
        if (piv != k && t < 17) {
            float tmp = S.A[k*18+t];
            S.A[k*18+t] = S.A[piv*18+t];
            S.A[piv*18+t] = tmp;
        }
        __syncthreads();
        const float pkk = S.A[k*18+k];
        if (t == 0) { float dn = S.det * pkk; S.det = (piv != k) ? -dn : dn; }
        if (n > k) {
            float f = S.A[n*18+k] / pkk;
            if (o > k)       S.A[n*18+o]  -= f * S.A[k*18+o];
            else if (o == k) S.A[n*18+16] -= f * S.A[k*18+16];
        }
        __syncthreads();
    }

    // ---- Phase 4: back-substitution (warp 0), out = M0 * det * x ----
    if (t < 32) {
        const float detv = S.det;
        float rhs = (t < 16) ? S.A[t*18+16] * detv : 0.f;
        float xl = 0.f;
        #pragma unroll 1
        for (int c = 15; c >= 0; --c) {
            float xc = __shfl_sync(0xffffffffu, rhs, c) / S.A[c*18+c];
            if (t == c) xl = xc;
            if (t < c) rhs = fmaf(-S.A[t*18+c], xc, rhs);
        }
        if (t < 16) out[(size_t)p*16 + t] = S.M0[t] * xl;
    }
}

extern "C" void kernel_launch(void* const* d_in, const int* in_sizes, int n_in,
                              void* d_out, int out_size) {
    const float* eq  = (const float*)d_in[0];
    const float* rei = (const float*)d_in[1];
    const float* Wg  = (const float*)d_in[2];
    const float* bg  = (const float*)d_in[3];
    const float* edg = (const float*)d_in[4];
    const float* eig = (const float*)d_in[5];
    float* out = (float*)d_out;
    const int smem = (int)sizeof(Smem);
    cudaFuncSetAttribute(cof_kernel, cudaFuncAttributeMaxDynamicSharedMemorySize, smem);
    cof_kernel<<<8192, 256, smem>>>(eq, rei, Wg, bg, edg, eig, out);
}

// round 8
// speedup vs baseline: 2.0300x; 2.0300x over previous
#include <cuda_runtime.h>

// B=4096, NSPIN=2, NPS=16, D=256, NION=8, DIM=3.  8192 (b,s) pairs.
// k1: one block per pair -> M^T (16x16) to scratch.
// k2: warp-sync LU, 2 pairs/warp -> cofactors.

__device__ float g_M[8192 * 256];   // M^T per pair, row-major [o][n]

struct __align__(16) Smem1 {
    float xsT[256 * 17];      // [d][n], pitch 17
    float W[256 * 17];        // [d][o], pitch 17
    float part[8 * 16 * 16];  // [kg][n][o]
    float rs[16 * 24];        // [n][i*3+d]
    float ed[8 * 16 * 9];     // [i][o][e*3+d]
    float ei[8 * 16];         // [i][o]
};

__global__ void __launch_bounds__(256, 4)
k1_buildM(const float* __restrict__ eq,  const float* __restrict__ rei,
          const float* __restrict__ Wg,  const float* __restrict__ bg,
          const float* __restrict__ edg, const float* __restrict__ eig)
{
    extern __shared__ __align__(16) char smem_raw[];
    Smem1& S = *reinterpret_cast<Smem1*>(smem_raw);
    const int p = blockIdx.x, s = p & 1, t = threadIdx.x;

    // ---- Phase 0: loads ----
    {
        const float* xsrc = eq + (size_t)p * 4096;
        #pragma unroll
        for (int c = 0; c < 4; ++c) {
            int idx = c * 1024 + t * 4;
            float4 v = *reinterpret_cast<const float4*>(xsrc + idx);
            int n = idx >> 8, d = idx & 255;
            S.xsT[(d+0)*17+n]=v.x; S.xsT[(d+1)*17+n]=v.y;
            S.xsT[(d+2)*17+n]=v.z; S.xsT[(d+3)*17+n]=v.w;
        }
        const float* wsrc = Wg + s * 4096;
        #pragma unroll
        for (int c = 0; c < 4; ++c) {
            int idx = c * 1024 + t * 4;
            float4 v = *reinterpret_cast<const float4*>(wsrc + idx);
            int d = idx >> 4, o = idx & 15;
            S.W[d*17+o+0]=v.x; S.W[d*17+o+1]=v.y;
            S.W[d*17+o+2]=v.z; S.W[d*17+o+3]=v.w;
        }
        if (t < 96)
            *reinterpret_cast<float4*>(&S.rs[t*4]) =
                *reinterpret_cast<const float4*>(rei + (size_t)p*384 + t*4);
        for (int i = t * 4; i < 1152; i += 1024)
            *reinterpret_cast<float4*>(&S.ed[i]) =
                *reinterpret_cast<const float4*>(edg + s*1152 + i);
        if (t < 32)
            *reinterpret_cast<float4*>(&S.ei[t*4]) =
                *reinterpret_cast<const float4*>(eig + s*128 + t*4);
    }
    __syncthreads();

    // ---- Phase 1: GEMM. warp = K-group (32 d), thread tile 4n x 2o ----
    {
        const int kg = t >> 5, l = t & 31;
        const int tn = (l >> 3) << 2, to = (l & 7) << 1;
        float a0x=0.f,a0y=0.f,a1x=0.f,a1y=0.f,a2x=0.f,a2y=0.f,a3x=0.f,a3y=0.f;
        const int d0 = kg << 5;
        #pragma unroll
        for (int j = 0; j < 32; ++j) {
            const float* xr = &S.xsT[(d0+j)*17 + tn];
            const float* wr = &S.W  [(d0+j)*17 + to];
            float x0=xr[0],x1=xr[1],x2=xr[2],x3=xr[3];
            float w0=wr[0],w1=wr[1];
            a0x=fmaf(x0,w0,a0x); a0y=fmaf(x0,w1,a0y);
            a1x=fmaf(x1,w0,a1x); a1y=fmaf(x1,w1,a1y);
            a2x=fmaf(x2,w0,a2x); a2y=fmaf(x2,w1,a2y);
            a3x=fmaf(x3,w0,a3x); a3y=fmaf(x3,w1,a3y);
        }
        S.part[(kg*16+tn+0)*16+to]=a0x; S.part[(kg*16+tn+0)*16+to+1]=a0y;
        S.part[(kg*16+tn+1)*16+to]=a1x; S.part[(kg*16+tn+1)*16+to+1]=a1y;
        S.part[(kg*16+tn+2)*16+to]=a2x; S.part[(kg*16+tn+2)*16+to+1]=a2y;
        S.part[(kg*16+tn+3)*16+to]=a3x; S.part[(kg*16+tn+3)*16+to+1]=a3y;
    }
    __syncthreads();

    // ---- Phase 2: reduce + envelope + M ----
    const int n = t >> 4, o = t & 15;
    float Mv;
    {
        float y = bg[s*16 + o];
        #pragma unroll
        for (int k = 0; k < 8; ++k) y += S.part[(k*16 + n)*16 + o];

        float env = 0.f;
        #pragma unroll
        for (int i = 0; i < 8; ++i) {
            float r0=S.rs[n*24+i*3+0], r1=S.rs[n*24+i*3+1], r2=S.rs[n*24+i*3+2];
            const float* E = &S.ed[(i*16+o)*9];
            float a0 = fmaf(E[0],r0, fmaf(E[1],r1, E[2]*r2));
            float a1 = fmaf(E[3],r0, fmaf(E[4],r1, E[5]*r2));
            float a2 = fmaf(E[6],r0, fmaf(E[7],r1, E[8]*r2));
            float q  = fmaf(a0,a0, fmaf(a1,a1, a2*a2));
            env = fmaf(expf(-sqrtf(q)), S.ei[i*16+o], env);
        }
        Mv = y * env;
    }
    __syncthreads();                 // all part reads done before aliasing
    S.part[o*16 + n] = Mv;           // stage M^T [o][n]
    __syncthreads();
    if (t < 64)
        *reinterpret_cast<float4*>(&g_M[(size_t)p*256 + t*4]) =
            *reinterpret_cast<const float4*>(&S.part[t*4]);
}

// ---- k2: warp-synchronous LU + solve; 2 pairs per warp, 16 lanes each ----
__global__ void __launch_bounds__(256)
k2_solve(float* __restrict__ out)
{
    const int t = threadIdx.x;
    const int w = t >> 5, g = (t >> 4) & 1, r = t & 15;
    const int p = blockIdx.x * 16 + w * 2 + g;
    const float* Mp = &g_M[(size_t)p * 256];

    float A[16];                       // lane r owns row r of M^T
    #pragma unroll
    for (int j = 0; j < 16; j += 4) {
        float4 v = *reinterpret_cast<const float4*>(Mp + r*16 + j);
        A[j]=v.x; A[j+1]=v.y; A[j+2]=v.z; A[j+3]=v.w;
    }
    float m0  = Mp[r];                 // M^T[0][r] = M[r][0]
    float rhs = (r == 0) ? 1.f : 0.f;  // e0
    int mystep = -1;
    float det = 1.f;
    unsigned remaining = 0xFFFFu, parity = 0;

    #pragma unroll
    for (int k = 0; k < 16; ++k) {
        // argmax |A[k]| over active lanes (4-step bfly within 16-lane group)
        float v = (mystep < 0) ? fabsf(A[k]) : -1.f;
        int idx = r;
        #pragma unroll
        for (int wd = 8; wd >= 1; wd >>= 1) {
            float ov = __shfl_xor_sync(0xFFFFFFFFu, v,   wd, 16);
            int   oi = __shfl_xor_sync(0xFFFFFFFFu, idx, wd, 16);
            if (ov > v || (ov == v && oi < idx)) { v = ov; idx = oi; }
        }
        const int pl = idx;
        const float pkk = __shfl_sync(0xFFFFFFFFu, A[k], pl, 16);
        det *= pkk;
        parity += __popc(remaining & ((1u << pl) - 1u));
        remaining &= ~(1u << pl);
        const bool active = (mystep < 0) && (r != pl);
        if (r == pl) mystep = k;
        const float f = __fdividef(A[k], pkk);
        #pragma unroll
        for (int j = k + 1; j < 16; ++j) {
            float pv = __shfl_sync(0xFFFFFFFFu, A[j], pl, 16);
            if (active) A[j] = fmaf(-f, pv, A[j]);
        }
        float pr = __shfl_sync(0xFFFFFFFFu, rhs, pl, 16);
        if (active) rhs = fmaf(-f, pr, rhs);
    }

    const float sdet = (parity & 1u) ? -det : det;
    float xk = 0.f;
    #pragma unroll
    for (int c = 15; c >= 0; --c) {
        unsigned b = __ballot_sync(0xFFFFFFFFu, mystep == c);
        int src = __ffs((b >> (g * 16)) & 0xFFFFu) - 1;
        float num = __shfl_sync(0xFFFFFFFFu, rhs,  src, 16);
        float den = __shfl_sync(0xFFFFFFFFu, A[c], src, 16);
        float xc  = __fdividef(num, den);
        if (r == c) xk = xc;                 // x component index = lane id
        if (mystep < c) rhs = fmaf(-A[c], xc, rhs);
    }
    out[(size_t)p * 16 + r] = m0 * sdet * xk;
}

extern "C" void kernel_launch(void* const* d_in, const int* in_sizes, int n_in,
                              void* d_out, int out_size) {
    const float* eq  = (const float*)d_in[0];
    const float* rei = (const float*)d_in[1];
    const float* Wg  = (const float*)d_in[2];
    const float* bg  = (const float*)d_in[3];
    const float* edg = (const float*)d_in[4];
    const float* eig = (const float*)d_in[5];
    float* out = (float*)d_out;
    const int smem = (int)sizeof(Smem1);
    cudaFuncSetAttribute(k1_buildM, cudaFuncAttributeMaxDynamicSharedMemorySize, smem);
    k1_buildM<<<8192, 256, smem>>>(eq, rei, Wg, bg, edg, eig);
    k2_solve<<<512, 256>>>(out);
}